// round 4
// baseline (speedup 1.0000x reference)
#include <cuda_runtime.h>
#include <cstdint>

// Problem constants
#define B_  2
#define S_  2048
#define DM  768
#define H_  12
#define DK  64

// Scratch (allocation-free rule: device globals)
__device__ float g_Q[B_ * S_ * DM];
__device__ float g_K[B_ * S_ * DM];
__device__ float g_V[B_ * S_ * DM];
__device__ float g_X[B_ * S_ * DM];

// ---------------------------------------------------------------------------
// Packed fp32x2 helpers (sm_100+ PTX; SASS FFMA2 — 2 fp32 FMAs per issue)
// ---------------------------------------------------------------------------
typedef unsigned long long u64;

#define FMA2(d, a, b, c) \
    asm("fma.rn.f32x2 %0, %1, %2, %3;" : "=l"(d) : "l"(a), "l"(b), "l"(c))
#define MUL2(d, a, b) \
    asm("mul.rn.f32x2 %0, %1, %2;" : "=l"(d) : "l"(a), "l"(b))
#define PACK2(d, lo, hi) \
    asm("mov.b64 %0, {%1, %2};" : "=l"(d) : "f"(lo), "f"(hi))
#define UNPACK2(lo, hi, s) \
    asm("mov.b64 {%0, %1}, %2;" : "=f"(lo), "=f"(hi) : "l"(s))
// 16B shared load -> two packed f32x2 pairs
#define LDS_V2B64(d0, d1, addr) \
    asm volatile("ld.shared.v2.b64 {%0, %1}, [%2];" \
                 : "=l"(d0), "=l"(d1) : "r"(addr))
// 8B shared load -> one packed pair
#define LDS_B64(d0, addr) \
    asm volatile("ld.shared.b64 %0, [%2];" : "=l"(d0) : "r"(addr), "r"(addr))

// ---------------------------------------------------------------------------
// GEMM: C[M,N] = A[M,K] @ W[N,K]^T + bias[N]
// 128x128 tile, BK=8, 256 threads, 8x8 microtile, double-buffered smem,
// fp32x2 packed math. W is staged DUPLICATED ({w,w} pairs) so the inner loop
// needs zero packing MOVs.
// ---------------------------------------------------------------------------
__global__ __launch_bounds__(256) void gemm_nt_bias(
    const float* __restrict__ A, const float* __restrict__ W,
    const float* __restrict__ bias, float* __restrict__ C,
    int M, int N, int K)
{
    __shared__ float As[2][8][128];     // 8 KB
    __shared__ float Ws2[2][8][256];    // 16 KB, each W value duplicated

    const int t  = threadIdx.x;
    const int tx = t & 15;        // N microtile
    const int ty = t >> 4;        // M microtile
    const int bm = blockIdx.y * 128;
    const int bn = blockIdx.x * 128;

    const int lrow = t >> 1;        // 0..127
    const int lk   = (t & 1) * 4;   // 0 or 4

    // acc2[i2][j]: packed pair of rows (ty*8+2*i2, ty*8+2*i2+1), col tx*8+j
    u64 acc2[4][8];
#pragma unroll
    for (int i = 0; i < 4; i++)
#pragma unroll
        for (int j = 0; j < 8; j++) acc2[i][j] = 0ull;

    const float* Aptr = A + (size_t)(bm + lrow) * K + lk;
    const float* Wptr = W + (size_t)(bn + lrow) * K + lk;

    // stage tile 0
    {
        float4 av = *(const float4*)(Aptr);
        float4 wv = *(const float4*)(Wptr);
        As[0][lk + 0][lrow] = av.x; As[0][lk + 1][lrow] = av.y;
        As[0][lk + 2][lrow] = av.z; As[0][lk + 3][lrow] = av.w;
        *(float2*)&Ws2[0][lk + 0][2 * lrow] = make_float2(wv.x, wv.x);
        *(float2*)&Ws2[0][lk + 1][2 * lrow] = make_float2(wv.y, wv.y);
        *(float2*)&Ws2[0][lk + 2][2 * lrow] = make_float2(wv.z, wv.z);
        *(float2*)&Ws2[0][lk + 3][2 * lrow] = make_float2(wv.w, wv.w);
    }
    __syncthreads();

    const uint32_t aB0 = (uint32_t)__cvta_generic_to_shared(&As[0][0][ty * 8]);
    const uint32_t aB1 = (uint32_t)__cvta_generic_to_shared(&As[1][0][ty * 8]);
    const uint32_t bB0 = (uint32_t)__cvta_generic_to_shared(&Ws2[0][0][tx * 16]);
    const uint32_t bB1 = (uint32_t)__cvta_generic_to_shared(&Ws2[1][0][tx * 16]);

    int cur = 0;
    for (int kt = 0; kt < K; kt += 8) {
        const bool has_next = (kt + 8) < K;
        float4 av2, wv2;
        if (has_next) {
            av2 = *(const float4*)(Aptr + kt + 8);
            wv2 = *(const float4*)(Wptr + kt + 8);
        }

        const uint32_t aB = cur ? aB1 : aB0;
        const uint32_t bB = cur ? bB1 : bB0;
#pragma unroll
        for (int k = 0; k < 8; k++) {
            u64 a[4], b[8];
            LDS_V2B64(a[0], a[1], aB + k * 512);
            LDS_V2B64(a[2], a[3], aB + k * 512 + 16);
            LDS_V2B64(b[0], b[1], bB + k * 1024);
            LDS_V2B64(b[2], b[3], bB + k * 1024 + 16);
            LDS_V2B64(b[4], b[5], bB + k * 1024 + 32);
            LDS_V2B64(b[6], b[7], bB + k * 1024 + 48);
#pragma unroll
            for (int j = 0; j < 8; j++)
#pragma unroll
                for (int i = 0; i < 4; i++)
                    FMA2(acc2[i][j], a[i], b[j], acc2[i][j]);
        }

        if (has_next) {
            const int nxt = cur ^ 1;
            As[nxt][lk + 0][lrow] = av2.x; As[nxt][lk + 1][lrow] = av2.y;
            As[nxt][lk + 2][lrow] = av2.z; As[nxt][lk + 3][lrow] = av2.w;
            *(float2*)&Ws2[nxt][lk + 0][2 * lrow] = make_float2(wv2.x, wv2.x);
            *(float2*)&Ws2[nxt][lk + 1][2 * lrow] = make_float2(wv2.y, wv2.y);
            *(float2*)&Ws2[nxt][lk + 2][2 * lrow] = make_float2(wv2.z, wv2.z);
            *(float2*)&Ws2[nxt][lk + 3][2 * lrow] = make_float2(wv2.w, wv2.w);
        }
        __syncthreads();
        cur ^= 1;
    }

    float bv[8];
#pragma unroll
    for (int j = 0; j < 8; j++) bv[j] = bias[bn + tx * 8 + j];

#pragma unroll
    for (int i2 = 0; i2 < 4; i2++) {
        float lo[8], hi[8];
#pragma unroll
        for (int j = 0; j < 8; j++) UNPACK2(lo[j], hi[j], acc2[i2][j]);

        float* r0 = C + (size_t)(bm + ty * 8 + 2 * i2 + 0) * N + bn + tx * 8;
        float* r1 = C + (size_t)(bm + ty * 8 + 2 * i2 + 1) * N + bn + tx * 8;
        float4 o0 = { lo[0] + bv[0], lo[1] + bv[1], lo[2] + bv[2], lo[3] + bv[3] };
        float4 o1 = { lo[4] + bv[4], lo[5] + bv[5], lo[6] + bv[6], lo[7] + bv[7] };
        float4 o2 = { hi[0] + bv[0], hi[1] + bv[1], hi[2] + bv[2], hi[3] + bv[3] };
        float4 o3 = { hi[4] + bv[4], hi[5] + bv[5], hi[6] + bv[6], hi[7] + bv[7] };
        *(float4*)(r0 + 0) = o0;
        *(float4*)(r0 + 4) = o1;
        *(float4*)(r1 + 0) = o2;
        *(float4*)(r1 + 4) = o3;
    }
}

// ---------------------------------------------------------------------------
// Causal flash attention v3: fp32x2 packed math, 16-key chunks.
// One thread per query row, 128 queries/block; K/V staged 64 keys at a time.
// Per chunk: 16 independent packed score chains, one max/rescale, 16 exps.
// ---------------------------------------------------------------------------
template<bool MASKED>
__device__ __forceinline__ void process16(
    uint32_t ksC, uint32_t vsC,          // smem addr of this chunk's key 0
    const u64* __restrict__ q2, u64* __restrict__ o2,
    float& m, float& l, int rel_end)     // valid keys: j < rel_end (MASKED)
{
    u64 s2[16];
#pragma unroll
    for (int j = 0; j < 16; j++) s2[j] = 0ull;

    // Scores: d-outer, j-inner -> 16 independent packed chains.
#pragma unroll
    for (int d = 0; d < 16; d++) {
        const u64 qa = q2[2 * d], qb = q2[2 * d + 1];
#pragma unroll
        for (int j = 0; j < 16; j++) {
            u64 ka, kb;
            LDS_V2B64(ka, kb, ksC + j * 256 + d * 16);
            FMA2(s2[j], qa, ka, s2[j]);
            FMA2(s2[j], qb, kb, s2[j]);
        }
    }

    float s[16];
    float cmax = -1e30f;
#pragma unroll
    for (int j = 0; j < 16; j++) {
        float lo, hi;
        UNPACK2(lo, hi, s2[j]);
        float sj = (lo + hi) * 0.125f;            // 1/sqrt(64)
        if (MASKED) { if (j >= rel_end) sj = -1e30f; }
        s[j] = sj;
        cmax = fmaxf(cmax, sj);
    }

    const float newm = fmaxf(m, cmax);
    const float corr = __expf(m - newm);          // 0 on first chunk
    m = newm;
    l *= corr;
    u64 corr2; PACK2(corr2, corr, corr);
#pragma unroll
    for (int d = 0; d < 32; d++) MUL2(o2[d], o2[d], corr2);

    float lsum = 0.f;
#pragma unroll
    for (int j = 0; j < 16; j++) {
        s[j] = __expf(s[j] - newm);               // masked -> 0
        lsum += s[j];
    }
    l += lsum;

    // PV: j-outer, d-inner -> o2 reuse distance 32 packed FMAs.
#pragma unroll
    for (int j = 0; j < 16; j++) {
        u64 p2; PACK2(p2, s[j], s[j]);
#pragma unroll
        for (int d = 0; d < 16; d++) {
            u64 va, vb;
            LDS_V2B64(va, vb, vsC + j * 256 + d * 16);
            FMA2(o2[2 * d],     p2, va, o2[2 * d]);
            FMA2(o2[2 * d + 1], p2, vb, o2[2 * d + 1]);
        }
    }
}

__global__ __launch_bounds__(128) void attn_kernel(
    const float* __restrict__ Q, const float* __restrict__ K,
    const float* __restrict__ V, float* __restrict__ X)
{
    __shared__ float Ks[64 * 64];
    __shared__ float Vs[64 * 64];

    const int tid = threadIdx.x;
    const int h   = blockIdx.y;
    const int b   = blockIdx.z;
    // Reverse x so heaviest (most-keys) blocks launch first (LPT).
    const int qblk = (int)gridDim.x - 1 - (int)blockIdx.x;
    const int q0   = qblk * 128;
    const int qi   = q0 + tid;

    const uint32_t ksBase = (uint32_t)__cvta_generic_to_shared(Ks);
    const uint32_t vsBase = (uint32_t)__cvta_generic_to_shared(Vs);

    u64 q2[32];
    {
        const float4* qptr = (const float4*)(Q + ((size_t)(b * S_ + qi)) * DM + h * DK);
#pragma unroll
        for (int d4 = 0; d4 < 16; d4++) {
            float4 qv = qptr[d4];
            PACK2(q2[2 * d4],     qv.x, qv.y);
            PACK2(q2[2 * d4 + 1], qv.z, qv.w);
        }
    }

    u64 o2[32];
#pragma unroll
    for (int d = 0; d < 32; d++) o2[d] = 0ull;
    float m = -1e30f, l = 0.f;

    const int kmax = q0 + 128;

    for (int c0 = 0; c0 < kmax; c0 += 64) {
        const float4* kb4 = (const float4*)(K + ((size_t)(b * S_ + c0)) * DM + h * DK);
        const float4* vb4 = (const float4*)(V + ((size_t)(b * S_ + c0)) * DM + h * DK);
#pragma unroll
        for (int i = 0; i < 8; i++) {
            const int idx = tid + i * 128;        // 0..1023
            const int j   = idx >> 4;
            const int cc  = idx & 15;
            ((float4*)Ks)[idx] = kb4[(size_t)j * (DM / 4) + cc];
            ((float4*)Vs)[idx] = vb4[(size_t)j * (DM / 4) + cc];
        }
        __syncthreads();

        int jend = qi - c0 + 1;
        if (jend > 64) jend = 64;

        int jb = 0;
        for (; jb + 16 <= jend; jb += 16)
            process16<false>(ksBase + jb * 256, vsBase + jb * 256,
                             q2, o2, m, l, 16);
        const int rem = jend - jb;
        if (rem > 0)
            process16<true>(ksBase + jb * 256, vsBase + jb * 256,
                            q2, o2, m, l, rem);
        __syncthreads();
    }

    const float inv = 1.f / l;
    float* xptr = X + ((size_t)(b * S_ + qi)) * DM + h * DK;
#pragma unroll
    for (int d = 0; d < 16; d++) {
        float a0, a1, a2, a3;
        UNPACK2(a0, a1, o2[2 * d]);
        UNPACK2(a2, a3, o2[2 * d + 1]);
        float4 ov = { a0 * inv, a1 * inv, a2 * inv, a3 * inv };
        *(float4*)(xptr + d * 4) = ov;
    }
}

// ---------------------------------------------------------------------------
// Launch
// Inputs: 0:q 1:k 2:v 3:mask 4:wq 5:bq 6:wk 7:bk 8:wv 9:bv 10:wo 11:bo
// ---------------------------------------------------------------------------
extern "C" void kernel_launch(void* const* d_in, const int* in_sizes, int n_in,
                              void* d_out, int out_size)
{
    const float* q  = (const float*)d_in[0];
    const float* k  = (const float*)d_in[1];
    const float* v  = (const float*)d_in[2];
    const float* wq = (const float*)d_in[4];
    const float* bq = (const float*)d_in[5];
    const float* wk = (const float*)d_in[6];
    const float* bk = (const float*)d_in[7];
    const float* wv = (const float*)d_in[8];
    const float* bv = (const float*)d_in[9];
    const float* wo = (const float*)d_in[10];
    const float* bo = (const float*)d_in[11];
    float* out = (float*)d_out;

    float *gQ, *gK, *gV, *gX;
    cudaGetSymbolAddress((void**)&gQ, g_Q);
    cudaGetSymbolAddress((void**)&gK, g_K);
    cudaGetSymbolAddress((void**)&gV, g_V);
    cudaGetSymbolAddress((void**)&gX, g_X);

    const int M = B_ * S_;  // 4096
    dim3 ggrid(DM / 128, M / 128);   // (6, 32)
    dim3 gblk(256);

    gemm_nt_bias<<<ggrid, gblk>>>(q, wq, bq, gQ, M, DM, DM);
    gemm_nt_bias<<<ggrid, gblk>>>(k, wk, bk, gK, M, DM, DM);
    gemm_nt_bias<<<ggrid, gblk>>>(v, wv, bv, gV, M, DM, DM);

    dim3 agrid(S_ / 128, H_, B_);    // (16, 12, 2)
    attn_kernel<<<agrid, 128>>>(gQ, gK, gV, gX);

    gemm_nt_bias<<<ggrid, gblk>>>(gX, wo, bo, out, M, DM, DM);
}

// round 5
// speedup vs baseline: 2.1877x; 2.1877x over previous
#include <cuda_runtime.h>
#include <cstdint>

// Problem constants
#define B_  2
#define S_  2048
#define DM  768
#define H_  12
#define DK  64

// Scratch (allocation-free rule: device globals)
__device__ float g_Q[B_ * S_ * DM];
__device__ float g_K[B_ * S_ * DM];
__device__ float g_V[B_ * S_ * DM];
__device__ float g_X[B_ * S_ * DM];

// ---------------------------------------------------------------------------
// Packed fp32x2 helpers (sm_100+ PTX; SASS FFMA2) — used by attention only.
// ---------------------------------------------------------------------------
typedef unsigned long long u64;

#define FMA2(d, a, b, c) \
    asm("fma.rn.f32x2 %0, %1, %2, %3;" : "=l"(d) : "l"(a), "l"(b), "l"(c))
#define MUL2(d, a, b) \
    asm("mul.rn.f32x2 %0, %1, %2;" : "=l"(d) : "l"(a), "l"(b))
#define PACK2(d, lo, hi) \
    asm("mov.b64 %0, {%1, %2};" : "=l"(d) : "f"(lo), "f"(hi))
#define UNPACK2(lo, hi, s) \
    asm("mov.b64 {%0, %1}, %2;" : "=f"(lo), "=f"(hi) : "l"(s))
#define LDS_V2B64(d0, d1, addr) \
    asm volatile("ld.shared.v2.b64 {%0, %1}, [%2];" \
                 : "=l"(d0), "=l"(d1) : "r"(addr))

// ---------------------------------------------------------------------------
// GEMM core: C[M,N] = A[M,K] @ W[N,K]^T + bias[N]
// 128x128 tile, BK=8, 256 threads, 8x8 microtile, double-buffered smem.
// Plain FFMA (proven fast); shared by the fused-QKV and single variants.
// ---------------------------------------------------------------------------
__device__ __forceinline__ void gemm_body(
    const float* __restrict__ A, const float* __restrict__ W,
    const float* __restrict__ bias, float* __restrict__ C,
    int M, int N, int K, int bm, int bn,
    float As[2][8][128], float Ws[2][8][128])
{
    const int t  = threadIdx.x;
    const int tx = t & 15;        // N microtile
    const int ty = t >> 4;        // M microtile

    const int lrow = t >> 1;        // 0..127
    const int lk   = (t & 1) * 4;   // 0 or 4

    float acc[8][8];
#pragma unroll
    for (int i = 0; i < 8; i++)
#pragma unroll
        for (int j = 0; j < 8; j++) acc[i][j] = 0.f;

    const float* Aptr = A + (size_t)(bm + lrow) * K + lk;
    const float* Wptr = W + (size_t)(bn + lrow) * K + lk;

    // preload tile 0
    {
        float4 av = *(const float4*)(Aptr);
        float4 wv = *(const float4*)(Wptr);
        As[0][lk + 0][lrow] = av.x; As[0][lk + 1][lrow] = av.y;
        As[0][lk + 2][lrow] = av.z; As[0][lk + 3][lrow] = av.w;
        Ws[0][lk + 0][lrow] = wv.x; Ws[0][lk + 1][lrow] = wv.y;
        Ws[0][lk + 2][lrow] = wv.z; Ws[0][lk + 3][lrow] = wv.w;
    }
    __syncthreads();

    int cur = 0;
    for (int kt = 0; kt < K; kt += 8) {
        const bool has_next = (kt + 8) < K;
        float4 av2, wv2;
        if (has_next) {
            av2 = *(const float4*)(Aptr + kt + 8);
            wv2 = *(const float4*)(Wptr + kt + 8);
        }

#pragma unroll
        for (int k = 0; k < 8; k++) {
            float a[8], b[8];
            *(float4*)&a[0] = *(const float4*)&As[cur][k][ty * 8 + 0];
            *(float4*)&a[4] = *(const float4*)&As[cur][k][ty * 8 + 4];
            *(float4*)&b[0] = *(const float4*)&Ws[cur][k][tx * 8 + 0];
            *(float4*)&b[4] = *(const float4*)&Ws[cur][k][tx * 8 + 4];
#pragma unroll
            for (int i = 0; i < 8; i++)
#pragma unroll
                for (int j = 0; j < 8; j++)
                    acc[i][j] = fmaf(a[i], b[j], acc[i][j]);
        }

        if (has_next) {
            const int nxt = cur ^ 1;
            As[nxt][lk + 0][lrow] = av2.x; As[nxt][lk + 1][lrow] = av2.y;
            As[nxt][lk + 2][lrow] = av2.z; As[nxt][lk + 3][lrow] = av2.w;
            Ws[nxt][lk + 0][lrow] = wv2.x; Ws[nxt][lk + 1][lrow] = wv2.y;
            Ws[nxt][lk + 2][lrow] = wv2.z; Ws[nxt][lk + 3][lrow] = wv2.w;
        }
        __syncthreads();
        cur ^= 1;
    }

    float bv[8];
#pragma unroll
    for (int j = 0; j < 8; j++) bv[j] = bias[bn + tx * 8 + j];

#pragma unroll
    for (int i = 0; i < 8; i++) {
        float* crow = C + (size_t)(bm + ty * 8 + i) * N + bn + tx * 8;
        float4 o0 = { acc[i][0] + bv[0], acc[i][1] + bv[1],
                      acc[i][2] + bv[2], acc[i][3] + bv[3] };
        float4 o1 = { acc[i][4] + bv[4], acc[i][5] + bv[5],
                      acc[i][6] + bv[6], acc[i][7] + bv[7] };
        *(float4*)(crow + 0) = o0;
        *(float4*)(crow + 4) = o1;
    }
}

// Fused QKV: one launch covers all three projections. blockIdx.x in [0,18):
// [0,6) -> Q, [6,12) -> K, [12,18) -> V. Fewer waves, less tail waste.
__global__ __launch_bounds__(256) void gemm_qkv(
    const float* __restrict__ q, const float* __restrict__ k,
    const float* __restrict__ v,
    const float* __restrict__ wq, const float* __restrict__ bq,
    const float* __restrict__ wk, const float* __restrict__ bk,
    const float* __restrict__ wv, const float* __restrict__ bv,
    float* __restrict__ gQ, float* __restrict__ gK, float* __restrict__ gV)
{
    __shared__ float As[2][8][128];
    __shared__ float Ws[2][8][128];

    const int bx  = blockIdx.x;
    const int sel = bx / 6;
    const int bn  = (bx % 6) * 128;
    const int bm  = blockIdx.y * 128;

    const float* A; const float* W; const float* bias; float* C;
    if (sel == 0)      { A = q; W = wq; bias = bq; C = gQ; }
    else if (sel == 1) { A = k; W = wk; bias = bk; C = gK; }
    else               { A = v; W = wv; bias = bv; C = gV; }

    gemm_body(A, W, bias, C, B_ * S_, DM, DM, bm, bn, As, Ws);
}

__global__ __launch_bounds__(256) void gemm_nt_bias(
    const float* __restrict__ A, const float* __restrict__ W,
    const float* __restrict__ bias, float* __restrict__ C,
    int M, int N, int K)
{
    __shared__ float As[2][8][128];
    __shared__ float Ws[2][8][128];
    gemm_body(A, W, bias, C, M, N, K,
              blockIdx.y * 128, blockIdx.x * 128, As, Ws);
}

// ---------------------------------------------------------------------------
// Causal flash attention v3 (unchanged from R3, measured 610us):
// fp32x2 packed math, 16-key chunks, 1 thread/query, 128 queries/block.
// ---------------------------------------------------------------------------
template<bool MASKED>
__device__ __forceinline__ void process16(
    uint32_t ksC, uint32_t vsC,
    const u64* __restrict__ q2, u64* __restrict__ o2,
    float& m, float& l, int rel_end)
{
    u64 s2[16];
#pragma unroll
    for (int j = 0; j < 16; j++) s2[j] = 0ull;

#pragma unroll
    for (int d = 0; d < 16; d++) {
        const u64 qa = q2[2 * d], qb = q2[2 * d + 1];
#pragma unroll
        for (int j = 0; j < 16; j++) {
            u64 ka, kb;
            LDS_V2B64(ka, kb, ksC + j * 256 + d * 16);
            FMA2(s2[j], qa, ka, s2[j]);
            FMA2(s2[j], qb, kb, s2[j]);
        }
    }

    float s[16];
    float cmax = -1e30f;
#pragma unroll
    for (int j = 0; j < 16; j++) {
        float lo, hi;
        UNPACK2(lo, hi, s2[j]);
        float sj = (lo + hi) * 0.125f;            // 1/sqrt(64)
        if (MASKED) { if (j >= rel_end) sj = -1e30f; }
        s[j] = sj;
        cmax = fmaxf(cmax, sj);
    }

    const float newm = fmaxf(m, cmax);
    const float corr = __expf(m - newm);          // 0 on first chunk
    m = newm;
    l *= corr;
    u64 corr2; PACK2(corr2, corr, corr);
#pragma unroll
    for (int d = 0; d < 32; d++) MUL2(o2[d], o2[d], corr2);

    float lsum = 0.f;
#pragma unroll
    for (int j = 0; j < 16; j++) {
        s[j] = __expf(s[j] - newm);               // masked -> 0
        lsum += s[j];
    }
    l += lsum;

#pragma unroll
    for (int j = 0; j < 16; j++) {
        u64 p2; PACK2(p2, s[j], s[j]);
#pragma unroll
        for (int d = 0; d < 16; d++) {
            u64 va, vb;
            LDS_V2B64(va, vb, vsC + j * 256 + d * 16);
            FMA2(o2[2 * d],     p2, va, o2[2 * d]);
            FMA2(o2[2 * d + 1], p2, vb, o2[2 * d + 1]);
        }
    }
}

__global__ __launch_bounds__(128) void attn_kernel(
    const float* __restrict__ Q, const float* __restrict__ K,
    const float* __restrict__ V, float* __restrict__ X)
{
    __shared__ float Ks[64 * 64];
    __shared__ float Vs[64 * 64];

    const int tid = threadIdx.x;
    const int h   = blockIdx.y;
    const int b   = blockIdx.z;
    const int qblk = (int)gridDim.x - 1 - (int)blockIdx.x;   // LPT order
    const int q0   = qblk * 128;
    const int qi   = q0 + tid;

    const uint32_t ksBase = (uint32_t)__cvta_generic_to_shared(Ks);
    const uint32_t vsBase = (uint32_t)__cvta_generic_to_shared(Vs);

    u64 q2[32];
    {
        const float4* qptr = (const float4*)(Q + ((size_t)(b * S_ + qi)) * DM + h * DK);
#pragma unroll
        for (int d4 = 0; d4 < 16; d4++) {
            float4 qv = qptr[d4];
            PACK2(q2[2 * d4],     qv.x, qv.y);
            PACK2(q2[2 * d4 + 1], qv.z, qv.w);
        }
    }

    u64 o2[32];
#pragma unroll
    for (int d = 0; d < 32; d++) o2[d] = 0ull;
    float m = -1e30f, l = 0.f;

    const int kmax = q0 + 128;

    for (int c0 = 0; c0 < kmax; c0 += 64) {
        const float4* kb4 = (const float4*)(K + ((size_t)(b * S_ + c0)) * DM + h * DK);
        const float4* vb4 = (const float4*)(V + ((size_t)(b * S_ + c0)) * DM + h * DK);
#pragma unroll
        for (int i = 0; i < 8; i++) {
            const int idx = tid + i * 128;        // 0..1023
            const int j   = idx >> 4;
            const int cc  = idx & 15;
            ((float4*)Ks)[idx] = kb4[(size_t)j * (DM / 4) + cc];
            ((float4*)Vs)[idx] = vb4[(size_t)j * (DM / 4) + cc];
        }
        __syncthreads();

        int jend = qi - c0 + 1;
        if (jend > 64) jend = 64;

        int jb = 0;
        for (; jb + 16 <= jend; jb += 16)
            process16<false>(ksBase + jb * 256, vsBase + jb * 256,
                             q2, o2, m, l, 16);
        const int rem = jend - jb;
        if (rem > 0)
            process16<true>(ksBase + jb * 256, vsBase + jb * 256,
                            q2, o2, m, l, rem);
        __syncthreads();
    }

    const float inv = 1.f / l;
    float* xptr = X + ((size_t)(b * S_ + qi)) * DM + h * DK;
#pragma unroll
    for (int d = 0; d < 16; d++) {
        float a0, a1, a2, a3;
        UNPACK2(a0, a1, o2[2 * d]);
        UNPACK2(a2, a3, o2[2 * d + 1]);
        float4 ov = { a0 * inv, a1 * inv, a2 * inv, a3 * inv };
        *(float4*)(xptr + d * 4) = ov;
    }
}

// ---------------------------------------------------------------------------
// Launch
// Inputs: 0:q 1:k 2:v 3:mask 4:wq 5:bq 6:wk 7:bk 8:wv 9:bv 10:wo 11:bo
// ---------------------------------------------------------------------------
extern "C" void kernel_launch(void* const* d_in, const int* in_sizes, int n_in,
                              void* d_out, int out_size)
{
    const float* q  = (const float*)d_in[0];
    const float* k  = (const float*)d_in[1];
    const float* v  = (const float*)d_in[2];
    const float* wq = (const float*)d_in[4];
    const float* bq = (const float*)d_in[5];
    const float* wk = (const float*)d_in[6];
    const float* bk = (const float*)d_in[7];
    const float* wv = (const float*)d_in[8];
    const float* bv = (const float*)d_in[9];
    const float* wo = (const float*)d_in[10];
    const float* bo = (const float*)d_in[11];
    float* out = (float*)d_out;

    float *gQ, *gK, *gV, *gX;
    cudaGetSymbolAddress((void**)&gQ, g_Q);
    cudaGetSymbolAddress((void**)&gK, g_K);
    cudaGetSymbolAddress((void**)&gV, g_V);
    cudaGetSymbolAddress((void**)&gX, g_X);

    const int M = B_ * S_;  // 4096

    dim3 qkvgrid(18, M / 128);       // (18, 32) fused QKV
    gemm_qkv<<<qkvgrid, 256>>>(q, k, v, wq, bq, wk, bk, wv, bv, gQ, gK, gV);

    dim3 agrid(S_ / 128, H_, B_);    // (16, 12, 2)
    attn_kernel<<<agrid, 128>>>(gQ, gK, gV, gX);

    dim3 ggrid(DM / 128, M / 128);   // (6, 32)
    gemm_nt_bias<<<ggrid, 256>>>(gX, wo, bo, out, M, DM, DM);
}